// round 5
// baseline (speedup 1.0000x reference)
#include <cuda_runtime.h>
#include <math.h>

#define BATCH 256
#define NNODE 184
#define HID   128
#define TH    24
#define TF    24
#define M_ROWS (BATCH*NNODE)      /* 47104 */
#define GCOLS  (3*HID)            /* 384 */

// ---------------- persistent device scratch (no runtime allocation) ----------------
__device__ float g_h[(size_t)M_ROWS*HID];        // GRU hidden state      (24.1 MB)
__device__ float g_xn[M_ROWS];                   // scalar node state
__device__ float g_G[(size_t)M_ROWS*GCOLS];      // gh = h @ Whh^T        (72.3 MB)
__device__ float g_x2[(size_t)M_ROWS*10];        // forecast GRU input
__device__ float g_comp1[NNODE*NNODE];           // cos(angles)
__device__ float g_comp2[NNODE*NNODE];           // cos(angles - pi/2)
__device__ float g_WT_hist[HID*GCOLS];           // Whh_hist transposed [k][col]
__device__ float g_WT_fore[HID*GCOLS];           // Whh transposed

__device__ __forceinline__ float sigf(float x) { return 1.0f/(1.0f+expf(-x)); }

// ---------------- prep: trig tables + weight transposes ----------------
__global__ void prep_kernel(const float* __restrict__ angles,
                            const float* __restrict__ Whh_hist,
                            const float* __restrict__ Whh_fore) {
    int i = blockIdx.x*blockDim.x + threadIdx.x;
    if (i < NNODE*NNODE) {
        float a = angles[i];
        g_comp1[i] = cosf(a);
        g_comp2[i] = cosf(a - 1.57079632679489662f);
    }
    if (i < HID*GCOLS) {
        int c = i / HID;        // output column (row of W)
        int k = i % HID;        // k index (col of W)
        g_WT_hist[k*GCOLS + c] = Whh_hist[i];
        g_WT_fore[k*GCOLS + c] = Whh_fore[i];
    }
}

__global__ void zero_state_kernel() {
    int i = blockIdx.x*blockDim.x + threadIdx.x;
    if (i < M_ROWS*HID) g_h[i] = 0.0f;
    if (i < M_ROWS)     g_xn[i] = 0.0f;
}

// ---------------- SGEMM: G[M,384] = g_h[M,128] @ WT[128,384] ----------------
// BM=128, BN=128, BK=16, 8x8 per-thread micro-tile, 256 threads.
// M = 368*128 exactly, N = 3*128 exactly, K = 8*16 exactly -> no bounds checks.
__global__ __launch_bounds__(256) void gemm_kernel(int useHist) {
    const float* __restrict__ Bt = useHist ? g_WT_hist : g_WT_fore;
    __shared__ float As[16][132];   // [k][m], padded
    __shared__ float Bs[16][128];   // [k][n]

    const int tid  = threadIdx.x;
    const int row0 = blockIdx.y * 128;
    const int col0 = blockIdx.x * 128;
    const int tr = (tid >> 4) << 3;      // 0..120
    const int tc = (tid & 15) << 3;      // 0..120
    const int am = tid >> 2;             // 0..63
    const int ak = (tid & 3) << 2;       // 0,4,8,12
    const int bk = tid >> 5;             // 0..7
    const int bn = (tid & 31) << 2;      // 0..124

    float acc[8][8];
#pragma unroll
    for (int i=0;i<8;i++)
#pragma unroll
        for (int j=0;j<8;j++) acc[i][j]=0.0f;

    for (int kk = 0; kk < HID; kk += 16) {
        float4 a0 = *(const float4*)(g_h + (size_t)(row0+am   )*HID + kk + ak);
        float4 a1 = *(const float4*)(g_h + (size_t)(row0+am+64)*HID + kk + ak);
        float4 b0 = *(const float4*)(Bt + (size_t)(kk+bk  )*GCOLS + col0 + bn);
        float4 b1 = *(const float4*)(Bt + (size_t)(kk+bk+8)*GCOLS + col0 + bn);
        As[ak+0][am]    = a0.x; As[ak+1][am]    = a0.y; As[ak+2][am]    = a0.z; As[ak+3][am]    = a0.w;
        As[ak+0][am+64] = a1.x; As[ak+1][am+64] = a1.y; As[ak+2][am+64] = a1.z; As[ak+3][am+64] = a1.w;
        *(float4*)(&Bs[bk  ][bn]) = b0;
        *(float4*)(&Bs[bk+8][bn]) = b1;
        __syncthreads();
#pragma unroll
        for (int k=0;k<16;k++) {
            float a[8], b[8];
            float4 av0 = *(const float4*)(&As[k][tr]);
            float4 av1 = *(const float4*)(&As[k][tr+4]);
            float4 bv0 = *(const float4*)(&Bs[k][tc]);
            float4 bv1 = *(const float4*)(&Bs[k][tc+4]);
            a[0]=av0.x; a[1]=av0.y; a[2]=av0.z; a[3]=av0.w;
            a[4]=av1.x; a[5]=av1.y; a[6]=av1.z; a[7]=av1.w;
            b[0]=bv0.x; b[1]=bv0.y; b[2]=bv0.z; b[3]=bv0.w;
            b[4]=bv1.x; b[5]=bv1.y; b[6]=bv1.z; b[7]=bv1.w;
#pragma unroll
            for (int i=0;i<8;i++)
#pragma unroll
                for (int j=0;j<8;j++)
                    acc[i][j] = fmaf(a[i], b[j], acc[i][j]);
        }
        __syncthreads();
    }
#pragma unroll
    for (int i=0;i<8;i++) {
        float* crow = g_G + (size_t)(row0+tr+i)*GCOLS + col0 + tc;
        *(float4*)(crow)   = make_float4(acc[i][0],acc[i][1],acc[i][2],acc[i][3]);
        *(float4*)(crow+4) = make_float4(acc[i][4],acc[i][5],acc[i][6],acc[i][7]);
    }
}

// ---------------- wind-gated graph + ChebConv(K=2) + gate -> x2 ----------------
// One block per batch element.
__global__ __launch_bounds__(256) void graph_kernel(const float* __restrict__ feature,
                                                    const float* __restrict__ adj,
                                                    const float* __restrict__ cw0,
                                                    const float* __restrict__ cw1,
                                                    const float* __restrict__ cb,
                                                    int t) {
    int b   = blockIdx.x;
    int tid = threadIdx.x;
    __shared__ float sx[NNODE][9];
    __shared__ float sdinv[NNODE];
    __shared__ float shneg[NNODE];       // (deg>0) ? 0 : -1
    __shared__ unsigned int sM[NNODE][6];

    const float* fb = feature + (((size_t)b*(TH+TF) + TH + t)*NNODE)*8;
    for (int i = tid; i < NNODE; i += 256) {
        sx[i][0] = g_xn[b*NNODE + i];
#pragma unroll
        for (int c=0;c<8;c++) sx[i][1+c] = fb[i*8 + c];
    }
    __syncthreads();

    // pass 1: per-source-node edge bitmask + degree
    for (int i = tid; i < NNODE; i += 256) {
        float u = sx[i][1];
        float v = sx[i][2];
        const float* c1 = g_comp1 + i*NNODE;
        const float* c2 = g_comp2 + i*NNODE;
        const float* ar = adj     + i*NNODE;
        int deg = 0;
        for (int q=0;q<6;q++) {
            unsigned bits = 0;
            int jend = (q==5) ? (NNODE - 160) : 32;
            for (int jj=0;jj<jend;jj++) {
                int j = q*32 + jj;
                float w = u*c1[j] + v*c2[j];
                if (w >= 0.5f && ar[j] > 0.0f) { deg++; bits |= (1u << jj); }
            }
            sM[i][q] = bits;
        }
        sdinv[i] = (deg > 0) ? (1.0f / sqrtf((float)deg)) : 0.0f;
        shneg[i] = (deg > 0) ? 0.0f : -1.0f;
    }
    __syncthreads();

    // pass 2: y[j] = -dinv[j] * sum_i dinv[i]*M[i,j]*x[i] + hneg[j]*x[j]; gate; write x2
    for (int j = tid; j < NNODE; j += 256) {
        float y[9];
#pragma unroll
        for (int c=0;c<9;c++) y[c]=0.0f;
        int q = j >> 5, sh = j & 31;
        for (int i=0;i<NNODE;i++) {
            float w = ((sM[i][q] >> sh) & 1u) ? sdinv[i] : 0.0f;
#pragma unroll
            for (int c=0;c<9;c++) y[c] = fmaf(w, sx[i][c], y[c]);
        }
        float dj = sdinv[j], hn = shneg[j];
        float acc = cb[0];
#pragma unroll
        for (int c=0;c<9;c++) {
            float yc = fmaf(-dj, y[c], hn*sx[j][c]);
            acc += sx[j][c]*cw0[c] + yc*cw1[c];
        }
        float g = sigf(acc);
        float* o = g_x2 + (size_t)(b*NNODE + j)*10;
#pragma unroll
        for (int c=0;c<9;c++) o[c] = sx[j][c];
        o[9] = g;
    }
}

// ---------------- fused GRU gates (history): input = [xn, pm25] ----------------
// 1024 threads = 8 rows x 128 hidden units per block.
__global__ __launch_bounds__(1024) void gates_hist_kernel(
        const float* __restrict__ pm25,
        const float* __restrict__ Wih, const float* __restrict__ bih,
        const float* __restrict__ bhh, const float* __restrict__ fcw,
        const float* __restrict__ fcb, int t) {
    __shared__ float sW[GCOLS*2];
    __shared__ float sbih[GCOLS];
    __shared__ float sbhh[GCOLS];
    __shared__ float sfcw[HID];
    __shared__ float sx[8][2];
    __shared__ float sred[8][4];
    int tid  = threadIdx.x;
    int row0 = blockIdx.x * 8;
    if (tid < GCOLS*2) sW[tid] = Wih[tid];
    if (tid < GCOLS) sbih[tid] = bih[tid];
    else if (tid < 2*GCOLS) sbhh[tid-GCOLS] = bhh[tid-GCOLS];
    if (tid < HID) sfcw[tid] = fcw[tid];
    if (tid < 8) {
        int row = row0 + tid;
        sx[tid][0] = g_xn[row];
        int bb = row / NNODE, nn = row % NNODE;
        sx[tid][1] = pm25[((size_t)bb*TH + t)*NNODE + nn];
    }
    __syncthreads();

    int r  = tid >> 7;
    int hh = tid & 127;
    int row = row0 + r;
    float x0 = sx[r][0], x1 = sx[r][1];
    float gir = sbih[hh]       + x0*sW[(hh)*2]         + x1*sW[(hh)*2+1];
    float giz = sbih[HID+hh]   + x0*sW[(HID+hh)*2]     + x1*sW[(HID+hh)*2+1];
    float gin = sbih[2*HID+hh] + x0*sW[(2*HID+hh)*2]   + x1*sW[(2*HID+hh)*2+1];
    const float* Grow = g_G + (size_t)row*GCOLS;
    float rr  = sigf(gir + Grow[hh]       + sbhh[hh]);
    float zz  = sigf(giz + Grow[HID+hh]   + sbhh[HID+hh]);
    float nn2 = tanhf(gin + rr*(Grow[2*HID+hh] + sbhh[2*HID+hh]));
    float hold = g_h[(size_t)row*HID + hh];
    float hnew = (1.0f - zz)*nn2 + zz*hold;
    g_h[(size_t)row*HID + hh] = hnew;

    float val = hnew * sfcw[hh];
#pragma unroll
    for (int o=16;o>0;o>>=1) val += __shfl_down_sync(0xffffffffu, val, o);
    if ((tid & 31) == 0) sred[r][(tid>>5)&3] = val;
    __syncthreads();
    if (hh == 0) g_xn[row] = sred[r][0]+sred[r][1]+sred[r][2]+sred[r][3] + fcb[0];
}

// ---------------- fused GRU gates (forecast): input = x2 (10 feats), writes pred ----------------
__global__ __launch_bounds__(1024) void gates_fore_kernel(
        const float* __restrict__ Wih, const float* __restrict__ bih,
        const float* __restrict__ bhh, const float* __restrict__ fcw,
        const float* __restrict__ fcb, float* __restrict__ out, int t) {
    __shared__ float sW[GCOLS*10];
    __shared__ float sbih[GCOLS];
    __shared__ float sbhh[GCOLS];
    __shared__ float sfcw[HID];
    __shared__ float sx[8][10];
    __shared__ float sred[8][4];
    int tid  = threadIdx.x;
    int row0 = blockIdx.x * 8;
    for (int i = tid; i < GCOLS*10; i += 1024) sW[i] = Wih[i];
    if (tid < GCOLS) sbih[tid] = bih[tid];
    else if (tid < 2*GCOLS) sbhh[tid-GCOLS] = bhh[tid-GCOLS];
    if (tid < HID) sfcw[tid] = fcw[tid];
    if (tid < 80) sx[tid/10][tid%10] = g_x2[(size_t)row0*10 + tid];
    __syncthreads();

    int r  = tid >> 7;
    int hh = tid & 127;
    int row = row0 + r;
    float gir = sbih[hh], giz = sbih[HID+hh], gin = sbih[2*HID+hh];
#pragma unroll
    for (int k=0;k<10;k++) {
        float xk = sx[r][k];
        gir = fmaf(xk, sW[(hh)*10 + k],        gir);
        giz = fmaf(xk, sW[(HID+hh)*10 + k],    giz);
        gin = fmaf(xk, sW[(2*HID+hh)*10 + k],  gin);
    }
    const float* Grow = g_G + (size_t)row*GCOLS;
    float rr  = sigf(gir + Grow[hh]       + sbhh[hh]);
    float zz  = sigf(giz + Grow[HID+hh]   + sbhh[HID+hh]);
    float nn2 = tanhf(gin + rr*(Grow[2*HID+hh] + sbhh[2*HID+hh]));
    float hold = g_h[(size_t)row*HID + hh];
    float hnew = (1.0f - zz)*nn2 + zz*hold;
    g_h[(size_t)row*HID + hh] = hnew;

    float val = hnew * sfcw[hh];
#pragma unroll
    for (int o=16;o>0;o>>=1) val += __shfl_down_sync(0xffffffffu, val, o);
    if ((tid & 31) == 0) sred[r][(tid>>5)&3] = val;
    __syncthreads();
    if (hh == 0) {
        float s = sred[r][0]+sred[r][1]+sred[r][2]+sred[r][3] + fcb[0];
        g_xn[row] = s;
        int bb = row / NNODE, nn = row % NNODE;
        out[((size_t)bb*TF + t)*NNODE + nn] = s;
    }
}

// ---------------- launch ----------------
extern "C" void kernel_launch(void* const* d_in, const int* in_sizes, int n_in,
                              void* d_out, int out_size) {
    const float* feature   = (const float*)d_in[0];
    const float* pm25      = (const float*)d_in[1];
    const float* adj       = (const float*)d_in[2];
    const float* angles    = (const float*)d_in[3];
    const float* W_ih_hist = (const float*)d_in[4];
    const float* W_hh_hist = (const float*)d_in[5];
    const float* b_ih_hist = (const float*)d_in[6];
    const float* b_hh_hist = (const float*)d_in[7];
    const float* fc_hist_w = (const float*)d_in[8];
    const float* fc_hist_b = (const float*)d_in[9];
    const float* cheb_w0   = (const float*)d_in[10];
    const float* cheb_w1   = (const float*)d_in[11];
    const float* cheb_b    = (const float*)d_in[12];
    const float* W_ih      = (const float*)d_in[13];
    const float* W_hh      = (const float*)d_in[14];
    const float* b_ih      = (const float*)d_in[15];
    const float* b_hh      = (const float*)d_in[16];
    const float* fc_out_w  = (const float*)d_in[17];
    const float* fc_out_b  = (const float*)d_in[18];
    float* out = (float*)d_out;

    prep_kernel<<<(HID*GCOLS + 255)/256, 256>>>(angles, W_hh_hist, W_hh);
    zero_state_kernel<<<(M_ROWS*HID + 255)/256, 256>>>();

    dim3 ggrid(GCOLS/128, M_ROWS/128);   // (3, 368)

    for (int t = 0; t < TH; t++) {
        gemm_kernel<<<ggrid, 256>>>(1);
        gates_hist_kernel<<<M_ROWS/8, 1024>>>(pm25, W_ih_hist, b_ih_hist,
                                              b_hh_hist, fc_hist_w, fc_hist_b, t);
    }
    for (int t = 0; t < TF; t++) {
        graph_kernel<<<BATCH, 256>>>(feature, adj, cheb_w0, cheb_w1, cheb_b, t);
        gemm_kernel<<<ggrid, 256>>>(0);
        gates_fore_kernel<<<M_ROWS/8, 1024>>>(W_ih, b_ih, b_hh,
                                              fc_out_w, fc_out_b, out, t);
    }
}